// round 7
// baseline (speedup 1.0000x reference)
#include <cuda_runtime.h>
#include <cuda_bf16.h>
#include <mma.h>
#include <cstdint>

using namespace nvcuda;

// Problem constants
#define BB 8
#define SS 1024
#define HH 1024
#define NH 16
#define HD 64
#define MM (BB*SS)   // 8192
#define KK HH        // 1024
#define NN HH        // 1024

// Scratch (no allocs allowed -> device globals)
__device__ float g_q[BB*NH*SS*HD];
__device__ float g_k[BB*NH*SS*HD];
__device__ float g_v[BB*NH*SS*HD];
__device__ float g_ctx[MM*HH];
__device__ float g_tmp[MM*HH];

// ===========================================================================
// WMMA bf16 GEMM: C = A @ W^T + bias (+ resid). A [M,K] rm, W [N,K] rm.
// CTA tile 128x128, BK=32, 8 warps -> each warp 64x32 (4x2 wmma 16x16x16).
// fp32 global -> bf16 smem convert on load; fp32 accumulate; smem-staged
// epilogue. MODE 0: scatter into [B,NH,S,HD]. MODE 1: [M,N] + residual.
// ===========================================================================
#define BKC 32
#define LDAB 40                          // bf16 elems per smem row (pad 8)
#define ABUF_BYTES (128 * LDAB * 2)      // 10240
#define SM_OFF(buf, t) ((buf) * 2 * ABUF_BYTES + (t) * ABUF_BYTES)
#define STAGE_LD 132                     // floats per stage row
#define GSM_TOTAL (128 * STAGE_LD * 4)   // 67584 (>= 4*ABUF_BYTES = 40960)

template<int MODE>
__global__ __launch_bounds__(256) void gemm_wmma(const float* __restrict__ A,
                                                 const float* __restrict__ W,
                                                 const float* __restrict__ bias,
                                                 const float* __restrict__ resid,
                                                 float* __restrict__ Cout)
{
    extern __shared__ char smem[];
    const int tid = threadIdx.x;
    const int wid = tid >> 5;
    const int m0 = blockIdx.y * 128;
    const int n0 = blockIdx.x * 128;

    const int warp_m = wid >> 2;      // 0..1  -> 64 rows
    const int warp_n = wid & 3;       // 0..3  -> 32 cols

    // ---- load mapping: 2 threads per row, each covers 16 cols (4 float4)
    const int lrow = tid >> 1;            // 0..127
    const int lc0  = (tid & 1) * 16;      // 0 or 16

    const float* Arow = A + (size_t)(m0 + lrow) * KK + lc0;
    const float* Wrow = W + (size_t)(n0 + lrow) * KK + lc0;

    wmma::fragment<wmma::accumulator, 16, 16, 16, float> acc[4][2];
#pragma unroll
    for (int i = 0; i < 4; i++)
#pragma unroll
        for (int j = 0; j < 2; j++) wmma::fill_fragment(acc[i][j], 0.f);

    float4 pa[4], pw[4];

    // prefetch chunk 0
#pragma unroll
    for (int j = 0; j < 4; j++) {
        pa[j] = *(const float4*)(Arow + j * 4);
        pw[j] = *(const float4*)(Wrow + j * 4);
    }

    const int nchunk = KK / BKC;      // 32
    for (int c = 0; c < nchunk; ++c) {
        const int buf = c & 1;
        // store prefetched chunk c into smem (convert to bf16)
        {
            __nv_bfloat16* as = (__nv_bfloat16*)(smem + SM_OFF(buf, 0)) + lrow * LDAB + lc0;
            __nv_bfloat16* ws = (__nv_bfloat16*)(smem + SM_OFF(buf, 1)) + lrow * LDAB + lc0;
#pragma unroll
            for (int j = 0; j < 4; j++) {
                __nv_bfloat162 a01 = __floats2bfloat162_rn(pa[j].x, pa[j].y);
                __nv_bfloat162 a23 = __floats2bfloat162_rn(pa[j].z, pa[j].w);
                __nv_bfloat162 w01 = __floats2bfloat162_rn(pw[j].x, pw[j].y);
                __nv_bfloat162 w23 = __floats2bfloat162_rn(pw[j].z, pw[j].w);
                *(uint2*)(as + j * 4) = make_uint2(*(uint32_t*)&a01, *(uint32_t*)&a23);
                *(uint2*)(ws + j * 4) = make_uint2(*(uint32_t*)&w01, *(uint32_t*)&w23);
            }
        }
        __syncthreads();

        // prefetch chunk c+1 while computing c
        if (c + 1 < nchunk) {
            const float* An = Arow + (c + 1) * BKC;
            const float* Wn = Wrow + (c + 1) * BKC;
#pragma unroll
            for (int j = 0; j < 4; j++) {
                pa[j] = *(const float4*)(An + j * 4);
                pw[j] = *(const float4*)(Wn + j * 4);
            }
        }

        const __nv_bfloat16* asb = (const __nv_bfloat16*)(smem + SM_OFF(buf, 0));
        const __nv_bfloat16* wsb = (const __nv_bfloat16*)(smem + SM_OFF(buf, 1));
#pragma unroll
        for (int ks = 0; ks < 2; ++ks) {
            wmma::fragment<wmma::matrix_a, 16, 16, 16, __nv_bfloat16, wmma::row_major> af[4];
            wmma::fragment<wmma::matrix_b, 16, 16, 16, __nv_bfloat16, wmma::col_major> bf[2];
#pragma unroll
            for (int i = 0; i < 4; i++)
                wmma::load_matrix_sync(af[i], asb + (warp_m * 64 + i * 16) * LDAB + ks * 16, LDAB);
#pragma unroll
            for (int j = 0; j < 2; j++)
                wmma::load_matrix_sync(bf[j], wsb + (warp_n * 32 + j * 16) * LDAB + ks * 16, LDAB);
#pragma unroll
            for (int i = 0; i < 4; i++)
#pragma unroll
                for (int j = 0; j < 2; j++)
                    wmma::mma_sync(acc[i][j], af[i], bf[j], acc[i][j]);
        }
        __syncthreads();
    }

    // ---- epilogue: stage 128x128 fp32 tile in smem, then fused writeback
    float* stage = (float*)smem;
#pragma unroll
    for (int i = 0; i < 4; i++)
#pragma unroll
        for (int j = 0; j < 2; j++)
            wmma::store_matrix_sync(stage + (warp_m * 64 + i * 16) * STAGE_LD
                                          + warp_n * 32 + j * 16,
                                    acc[i][j], STAGE_LD, wmma::mem_row_major);
    __syncthreads();

#pragma unroll
    for (int t = 0; t < 16; ++t) {
        const int e   = tid + t * 256;        // 0..4095 (float4 slots)
        const int row = e >> 5;               // 0..127
        const int c4  = e & 31;               // 0..31
        const float4 cv = *(const float4*)(stage + row * STAGE_LD + c4 * 4);
        const int m = m0 + row;
        const int n = n0 + c4 * 4;
        const float4 bv = *(const float4*)(bias + n);
        float4 o;
        o.x = cv.x + bv.x; o.y = cv.y + bv.y;
        o.z = cv.z + bv.z; o.w = cv.w + bv.w;
        if (MODE == 0) {
            const int bidx = m >> 10, s = m & 1023;
            const int h = n >> 6, d0 = n & 63;
            *(float4*)(Cout + (((size_t)(bidx * NH + h)) * SS + s) * HD + d0) = o;
        } else {
            const float4 rv = *(const float4*)(resid + (size_t)m * NN + n);
            o.x += rv.x; o.y += rv.y; o.z += rv.z; o.w += rv.w;
            *(float4*)(Cout + (size_t)m * NN + n) = o;
        }
    }
}

// ---------------------------------------------------------------------------
// Flash-style attention (SIMT fp32 — tensorize next round)
// ---------------------------------------------------------------------------
#define APAD 68
#define ATTN_SMEM ((4*64*APAD + 64) * (int)sizeof(float))

__global__ __launch_bounds__(256) void attn_kernel(const float* __restrict__ q,
                                                   const float* __restrict__ k,
                                                   const float* __restrict__ v,
                                                   const float* __restrict__ mask,
                                                   float* __restrict__ ctx)
{
    extern __shared__ float sm[];
    float* Qs  = sm;
    float* Ks  = Qs + 64 * APAD;
    float* Vs  = Ks + 64 * APAD;
    float* Ps  = Vs + 64 * APAD;
    float* Msk = Ps + 64 * APAD;

    const int tid  = threadIdx.x;
    const int qt   = blockIdx.x;
    const int h    = blockIdx.y;
    const int b_   = blockIdx.z;

    const float* qb = q + ((size_t)(b_ * NH + h) * SS + qt * 64) * HD;
    const float* kb = k + (size_t)(b_ * NH + h) * SS * HD;
    const float* vb = v + (size_t)(b_ * NH + h) * SS * HD;

    for (int i = tid; i < 1024; i += 256) {
        const int r = i >> 4, c = (i & 15) << 2;
        *(float4*)(Qs + r * APAD + c) = *(const float4*)(qb + r * 64 + c);
    }

    const int row  = tid >> 2;
    const int quad = tid & 3;

    float m_i = -1e30f, l_i = 0.f;
    float O[16];
#pragma unroll
    for (int dd = 0; dd < 16; dd++) O[dd] = 0.f;

    for (int kt = 0; kt < 16; kt++) {
        for (int i = tid; i < 1024; i += 256) {
            const int r = i >> 4, c = (i & 15) << 2;
            *(float4*)(Ks + r * APAD + c) = *(const float4*)(kb + kt * 4096 + r * 64 + c);
            *(float4*)(Vs + r * APAD + c) = *(const float4*)(vb + kt * 4096 + r * 64 + c);
        }
        if (tid < 64) Msk[tid] = mask[(size_t)b_ * SS + kt * 64 + tid];
        __syncthreads();

        float sv[16];
#pragma unroll
        for (int jj = 0; jj < 16; jj++) sv[jj] = 0.f;
#pragma unroll 4
        for (int d4 = 0; d4 < 16; d4++) {
            const float4 qv = *(const float4*)(Qs + row * APAD + d4 * 4);
#pragma unroll
            for (int jj = 0; jj < 16; jj++) {
                const float4 kv = *(const float4*)(Ks + (quad * 16 + jj) * APAD + d4 * 4);
                sv[jj] = fmaf(qv.x, kv.x, sv[jj]);
                sv[jj] = fmaf(qv.y, kv.y, sv[jj]);
                sv[jj] = fmaf(qv.z, kv.z, sv[jj]);
                sv[jj] = fmaf(qv.w, kv.w, sv[jj]);
            }
        }

        float tmax = -1e30f;
#pragma unroll
        for (int jj = 0; jj < 16; jj++) {
            sv[jj] = sv[jj] * 0.125f + Msk[quad * 16 + jj];
            tmax = fmaxf(tmax, sv[jj]);
        }
        tmax = fmaxf(tmax, __shfl_xor_sync(0xffffffffu, tmax, 1));
        tmax = fmaxf(tmax, __shfl_xor_sync(0xffffffffu, tmax, 2));

        const float m_new = fmaxf(m_i, tmax);
        const float corr  = __expf(m_i - m_new);
        float psum = 0.f;
#pragma unroll
        for (int jj = 0; jj < 16; jj++) {
            const float p = __expf(sv[jj] - m_new);
            sv[jj] = p;
            psum += p;
        }
        psum += __shfl_xor_sync(0xffffffffu, psum, 1);
        psum += __shfl_xor_sync(0xffffffffu, psum, 2);
        l_i = l_i * corr + psum;
        m_i = m_new;

#pragma unroll
        for (int jj4 = 0; jj4 < 4; jj4++)
            *(float4*)(Ps + row * APAD + quad * 16 + jj4 * 4) =
                make_float4(sv[jj4*4+0], sv[jj4*4+1], sv[jj4*4+2], sv[jj4*4+3]);
#pragma unroll
        for (int dd = 0; dd < 16; dd++) O[dd] *= corr;
        __syncthreads();

#pragma unroll 4
        for (int j = 0; j < 64; j++) {
            const float p = Ps[row * APAD + j];
            const float4 v0 = *(const float4*)(Vs + j * APAD + quad * 16 + 0);
            const float4 v1 = *(const float4*)(Vs + j * APAD + quad * 16 + 4);
            const float4 v2 = *(const float4*)(Vs + j * APAD + quad * 16 + 8);
            const float4 v3 = *(const float4*)(Vs + j * APAD + quad * 16 + 12);
            O[0]  = fmaf(p, v0.x, O[0]);  O[1]  = fmaf(p, v0.y, O[1]);
            O[2]  = fmaf(p, v0.z, O[2]);  O[3]  = fmaf(p, v0.w, O[3]);
            O[4]  = fmaf(p, v1.x, O[4]);  O[5]  = fmaf(p, v1.y, O[5]);
            O[6]  = fmaf(p, v1.z, O[6]);  O[7]  = fmaf(p, v1.w, O[7]);
            O[8]  = fmaf(p, v2.x, O[8]);  O[9]  = fmaf(p, v2.y, O[9]);
            O[10] = fmaf(p, v2.z, O[10]); O[11] = fmaf(p, v2.w, O[11]);
            O[12] = fmaf(p, v3.x, O[12]); O[13] = fmaf(p, v3.y, O[13]);
            O[14] = fmaf(p, v3.z, O[14]); O[15] = fmaf(p, v3.w, O[15]);
        }
        __syncthreads();
    }

    const float inv_l = 1.f / l_i;
    const int s_global = qt * 64 + row;
    float* outp = ctx + ((size_t)b_ * SS + s_global) * HH + h * HD + quad * 16;
    float4* op = (float4*)outp;
    op[0] = make_float4(O[0]*inv_l,  O[1]*inv_l,  O[2]*inv_l,  O[3]*inv_l);
    op[1] = make_float4(O[4]*inv_l,  O[5]*inv_l,  O[6]*inv_l,  O[7]*inv_l);
    op[2] = make_float4(O[8]*inv_l,  O[9]*inv_l,  O[10]*inv_l, O[11]*inv_l);
    op[3] = make_float4(O[12]*inv_l, O[13]*inv_l, O[14]*inv_l, O[15]*inv_l);
}

// ---------------------------------------------------------------------------
// LayerNorm
// ---------------------------------------------------------------------------
__global__ __launch_bounds__(256) void ln_kernel(const float* __restrict__ x,
                                                 const float* __restrict__ gamma,
                                                 const float* __restrict__ beta,
                                                 float* __restrict__ out)
{
    __shared__ float rs[8], rs2[8];
    const int r = blockIdx.x, tid = threadIdx.x;
    const float4* xr = (const float4*)(x + (size_t)r * HH);
    const float4 v = xr[tid];

    float s  = v.x + v.y + v.z + v.w;
    float s2 = v.x*v.x + v.y*v.y + v.z*v.z + v.w*v.w;
#pragma unroll
    for (int o = 16; o; o >>= 1) {
        s  += __shfl_xor_sync(0xffffffffu, s,  o);
        s2 += __shfl_xor_sync(0xffffffffu, s2, o);
    }
    if ((tid & 31) == 0) { rs[tid >> 5] = s; rs2[tid >> 5] = s2; }
    __syncthreads();
    float tot = 0.f, tot2 = 0.f;
#pragma unroll
    for (int i = 0; i < 8; i++) { tot += rs[i]; tot2 += rs2[i]; }

    const float mean = tot * (1.f / HH);
    const float var  = tot2 * (1.f / HH) - mean * mean;
    const float rstd = rsqrtf(var + 1e-12f);

    const float4 g  = ((const float4*)gamma)[tid];
    const float4 bt = ((const float4*)beta)[tid];
    float4 o;
    o.x = (v.x - mean) * rstd * g.x + bt.x;
    o.y = (v.y - mean) * rstd * g.y + bt.y;
    o.z = (v.z - mean) * rstd * g.z + bt.z;
    o.w = (v.w - mean) * rstd * g.w + bt.w;
    ((float4*)(out + (size_t)r * HH))[tid] = o;
}

// ---------------------------------------------------------------------------
extern "C" void kernel_launch(void* const* d_in, const int* in_sizes, int n_in,
                              void* d_out, int out_size)
{
    const float* hs    = (const float*)d_in[0];
    const float* mask  = (const float*)d_in[1];
    const float* Wq    = (const float*)d_in[2];
    const float* bq    = (const float*)d_in[3];
    const float* Wk    = (const float*)d_in[4];
    const float* bk    = (const float*)d_in[5];
    const float* Wv    = (const float*)d_in[6];
    const float* bv    = (const float*)d_in[7];
    const float* Wo    = (const float*)d_in[8];
    const float* bo    = (const float*)d_in[9];
    const float* gamma = (const float*)d_in[10];
    const float* beta  = (const float*)d_in[11];
    float* out = (float*)d_out;

    float *q, *k, *v, *ctx, *tmp;
    cudaGetSymbolAddress((void**)&q,   g_q);
    cudaGetSymbolAddress((void**)&k,   g_k);
    cudaGetSymbolAddress((void**)&v,   g_v);
    cudaGetSymbolAddress((void**)&ctx, g_ctx);
    cudaGetSymbolAddress((void**)&tmp, g_tmp);

    cudaFuncSetAttribute(gemm_wmma<0>,
                         cudaFuncAttributeMaxDynamicSharedMemorySize, GSM_TOTAL);
    cudaFuncSetAttribute(gemm_wmma<1>,
                         cudaFuncAttributeMaxDynamicSharedMemorySize, GSM_TOTAL);
    cudaFuncSetAttribute(attn_kernel,
                         cudaFuncAttributeMaxDynamicSharedMemorySize, ATTN_SMEM);

    dim3 gg(NN / 128, MM / 128);   // (8, 64)

    gemm_wmma<0><<<gg, 256, GSM_TOTAL>>>(hs, Wq, bq, nullptr, q);
    gemm_wmma<0><<<gg, 256, GSM_TOTAL>>>(hs, Wk, bk, nullptr, k);
    gemm_wmma<0><<<gg, 256, GSM_TOTAL>>>(hs, Wv, bv, nullptr, v);

    attn_kernel<<<dim3(16, 16, 8), 256, ATTN_SMEM>>>(q, k, v, mask, ctx);

    gemm_wmma<1><<<gg, 256, GSM_TOTAL>>>(ctx, Wo, bo, hs, tmp);

    ln_kernel<<<MM, 256>>>(tmp, gamma, beta, out);
}